// round 1
// baseline (speedup 1.0000x reference)
#include <cuda_runtime.h>
#include <math.h>

#define B_   4
#define T_   4096
#define C_   1024
#define H_   4096
#define E_   8
#define CAP_ 1024

// ---------------- scratch (static __device__, allocation-guard safe) ----------------
__device__ float g_probs[B_ * E_ * T_];                       // (B,E,T) expert-major probs
__device__ float g_topp[B_ * E_ * CAP_];
__device__ int   g_topi[B_ * E_ * CAP_];
__device__ float g_h[(size_t)B_ * E_ * CAP_ * H_];            // 512 MB hidden activations

// ---------------- gate + softmax ----------------
// one warp per token; gate_w kept transposed in smem for conflict-free reads
__global__ __launch_bounds__(256) void gate_kernel(const float* __restrict__ x,
                                                   const float* __restrict__ gw) {
    __shared__ float sgw[E_][C_];                             // 32 KB
    for (int i = threadIdx.x; i < C_ * E_; i += 256) {
        int c = i >> 3, e = i & 7;                            // gw is (C,E) row-major
        sgw[e][c] = gw[i];
    }
    __syncthreads();

    const int warp  = threadIdx.x >> 5;
    const int lane  = threadIdx.x & 31;
    const int token = blockIdx.x * 8 + warp;                  // 0 .. B*T-1
    const float* xrow = x + (size_t)token * C_;

    float acc[E_];
#pragma unroll
    for (int e = 0; e < E_; e++) acc[e] = 0.f;

    for (int c = lane; c < C_; c += 32) {
        float xv = xrow[c];
#pragma unroll
        for (int e = 0; e < E_; e++) acc[e] = fmaf(xv, sgw[e][c], acc[e]);
    }
#pragma unroll
    for (int off = 16; off > 0; off >>= 1) {
#pragma unroll
        for (int e = 0; e < E_; e++)
            acc[e] += __shfl_xor_sync(0xffffffffu, acc[e], off);
    }
    if (lane == 0) {
        float mx = acc[0];
#pragma unroll
        for (int e = 1; e < E_; e++) mx = fmaxf(mx, acc[e]);
        float s = 0.f, ex[E_];
#pragma unroll
        for (int e = 0; e < E_; e++) { ex[e] = expf(acc[e] - mx); s += ex[e]; }
        float inv = 1.0f / s;
        const int b = token >> 12;                            // T_ = 4096
        const int t = token & (T_ - 1);
#pragma unroll
        for (int e = 0; e < E_; e++)
            g_probs[((size_t)(b * E_ + e)) * T_ + t] = ex[e] * inv;
    }
}

// ---------------- top-k: full bitonic sort of 4096 packed keys ----------------
// key = (prob_bits << 32) | (0xFFFFFFFF - idx): descending sort => ties pick lower idx (JAX semantics)
__global__ __launch_bounds__(1024) void topk_kernel() {
    __shared__ unsigned long long keys[T_];                   // 32 KB
    const int g = blockIdx.x;                                 // (b*E + e)
    const float* p = g_probs + (size_t)g * T_;
    for (int i = threadIdx.x; i < T_; i += 1024) {
        unsigned pb = __float_as_uint(p[i]);                  // softmax probs > 0 -> order-preserving bits
        keys[i] = ((unsigned long long)pb << 32) | (unsigned)(0xFFFFFFFFu - (unsigned)i);
    }
    __syncthreads();
    for (int k = 2; k <= T_; k <<= 1) {
        for (int j = k >> 1; j > 0; j >>= 1) {
            for (int i = threadIdx.x; i < T_; i += 1024) {
                int ixj = i ^ j;
                if (ixj > i) {
                    unsigned long long a = keys[i], bb = keys[ixj];
                    bool dsc = ((i & k) == 0);
                    if (dsc ? (a < bb) : (a > bb)) { keys[i] = bb; keys[ixj] = a; }
                }
            }
            __syncthreads();
        }
    }
    for (int i = threadIdx.x; i < CAP_; i += 1024) {
        unsigned long long kv = keys[i];
        g_topp[(size_t)g * CAP_ + i] = __uint_as_float((unsigned)(kv >> 32));
        g_topi[(size_t)g * CAP_ + i] = (int)(0xFFFFFFFFu - (unsigned)kv);
    }
}

// ---------------- exact-erf GELU ----------------
__device__ __forceinline__ float gelu_f(float v) {
    return 0.5f * v * (1.0f + erff(v * 0.70710678118654752f));
}

// ---------------- GEMM1: h = gelu(gather(x) @ w1[e]), M=1024 N=4096 K=1024 ----------------
// 128x128 tile, BK=8, 256 threads, 8x8 microtile, double-buffered smem
__global__ __launch_bounds__(256, 2)
void gemm1_gelu(const float* __restrict__ x, const float* __restrict__ w1) {
    const int g  = blockIdx.z;
    const int b  = g >> 3, e = g & 7;
    const int m0 = blockIdx.y << 7;
    const int n0 = blockIdx.x << 7;

    __shared__ float As[2][8][128];
    __shared__ float Bs[2][8][128];
    __shared__ int   s_row[128];

    const int tid = threadIdx.x;
    if (tid < 128) s_row[tid] = g_topi[(size_t)g * CAP_ + m0 + tid];
    __syncthreads();

    const int am = tid >> 1,  ak = (tid & 1) << 2;            // A: 128 rows x 8k as float4
    const int bk = tid >> 5,  bn = (tid & 31) << 2;           // B: 8k x 128n as float4
    const float* Ap = x  + ((size_t)(b * T_ + s_row[am])) * C_ + ak;
    const float* Bp = w1 + (size_t)e * C_ * H_ + (size_t)bk * H_ + (n0 + bn);

    const int tr = (tid >> 4) << 3;
    const int tc = (tid & 15) << 3;

    float acc[8][8];
#pragma unroll
    for (int i = 0; i < 8; i++)
#pragma unroll
        for (int j = 0; j < 8; j++) acc[i][j] = 0.f;

    float4 av = *(const float4*)Ap;
    float4 bv = *(const float4*)Bp;
    As[0][ak + 0][am] = av.x; As[0][ak + 1][am] = av.y;
    As[0][ak + 2][am] = av.z; As[0][ak + 3][am] = av.w;
    *(float4*)&Bs[0][bk][bn] = bv;
    __syncthreads();

    int buf = 0;
    const int NK = C_ / 8;
    for (int kt = 0; kt < NK; kt++) {
        if (kt + 1 < NK) {
            av = *(const float4*)(Ap + (kt + 1) * 8);
            bv = *(const float4*)(Bp + (size_t)(kt + 1) * 8 * H_);
        }
#pragma unroll
        for (int kk = 0; kk < 8; kk++) {
            float a[8], bb[8];
            *(float4*)&a[0]  = *(const float4*)&As[buf][kk][tr];
            *(float4*)&a[4]  = *(const float4*)&As[buf][kk][tr + 4];
            *(float4*)&bb[0] = *(const float4*)&Bs[buf][kk][tc];
            *(float4*)&bb[4] = *(const float4*)&Bs[buf][kk][tc + 4];
#pragma unroll
            for (int i = 0; i < 8; i++)
#pragma unroll
                for (int j = 0; j < 8; j++)
                    acc[i][j] = fmaf(a[i], bb[j], acc[i][j]);
        }
        if (kt + 1 < NK) {
            int nb = buf ^ 1;
            As[nb][ak + 0][am] = av.x; As[nb][ak + 1][am] = av.y;
            As[nb][ak + 2][am] = av.z; As[nb][ak + 3][am] = av.w;
            *(float4*)&Bs[nb][bk][bn] = bv;
        }
        buf ^= 1;
        __syncthreads();
    }

    float* Cp = g_h + (size_t)g * CAP_ * H_;
#pragma unroll
    for (int i = 0; i < 8; i++) {
        size_t off = (size_t)(m0 + tr + i) * H_ + n0 + tc;
#pragma unroll
        for (int j4 = 0; j4 < 8; j4 += 4) {
            float4 v;
            v.x = gelu_f(acc[i][j4 + 0]);
            v.y = gelu_f(acc[i][j4 + 1]);
            v.z = gelu_f(acc[i][j4 + 2]);
            v.w = gelu_f(acc[i][j4 + 3]);
            *(float4*)(Cp + off + j4) = v;
        }
    }
}

// ---------------- GEMM2: out += scatter( (h @ w2[e]) * top_p ), M=1024 N=1024 K=4096 ----------------
__global__ __launch_bounds__(256, 2)
void gemm2_scatter(const float* __restrict__ w2, float* __restrict__ out) {
    const int g  = blockIdx.z;
    const int b  = g >> 3, e = g & 7;
    const int m0 = blockIdx.y << 7;
    const int n0 = blockIdx.x << 7;

    __shared__ float As[2][8][128];
    __shared__ float Bs[2][8][128];
    __shared__ int   s_tok[128];
    __shared__ float s_p[128];

    const int tid = threadIdx.x;
    if (tid < 128) {
        s_tok[tid] = g_topi[(size_t)g * CAP_ + m0 + tid];
        s_p[tid]   = g_topp[(size_t)g * CAP_ + m0 + tid];
    }
    __syncthreads();

    const int am = tid >> 1,  ak = (tid & 1) << 2;
    const int bk = tid >> 5,  bn = (tid & 31) << 2;
    const float* Ap = g_h + (size_t)g * CAP_ * H_ + (size_t)(m0 + am) * H_ + ak;
    const float* Bp = w2  + (size_t)e * H_ * C_ + (size_t)bk * C_ + (n0 + bn);

    const int tr = (tid >> 4) << 3;
    const int tc = (tid & 15) << 3;

    float acc[8][8];
#pragma unroll
    for (int i = 0; i < 8; i++)
#pragma unroll
        for (int j = 0; j < 8; j++) acc[i][j] = 0.f;

    float4 av = *(const float4*)Ap;
    float4 bv = *(const float4*)Bp;
    As[0][ak + 0][am] = av.x; As[0][ak + 1][am] = av.y;
    As[0][ak + 2][am] = av.z; As[0][ak + 3][am] = av.w;
    *(float4*)&Bs[0][bk][bn] = bv;
    __syncthreads();

    int buf = 0;
    const int NK = H_ / 8;
    for (int kt = 0; kt < NK; kt++) {
        if (kt + 1 < NK) {
            av = *(const float4*)(Ap + (kt + 1) * 8);
            bv = *(const float4*)(Bp + (size_t)(kt + 1) * 8 * C_);
        }
#pragma unroll
        for (int kk = 0; kk < 8; kk++) {
            float a[8], bb[8];
            *(float4*)&a[0]  = *(const float4*)&As[buf][kk][tr];
            *(float4*)&a[4]  = *(const float4*)&As[buf][kk][tr + 4];
            *(float4*)&bb[0] = *(const float4*)&Bs[buf][kk][tc];
            *(float4*)&bb[4] = *(const float4*)&Bs[buf][kk][tc + 4];
#pragma unroll
            for (int i = 0; i < 8; i++)
#pragma unroll
                for (int j = 0; j < 8; j++)
                    acc[i][j] = fmaf(a[i], bb[j], acc[i][j]);
        }
        if (kt + 1 < NK) {
            int nb = buf ^ 1;
            As[nb][ak + 0][am] = av.x; As[nb][ak + 1][am] = av.y;
            As[nb][ak + 2][am] = av.z; As[nb][ak + 3][am] = av.w;
            *(float4*)&Bs[nb][bk][bn] = bv;
        }
        buf ^= 1;
        __syncthreads();
    }

#pragma unroll
    for (int i = 0; i < 8; i++) {
        const int r   = tr + i;
        const int tok = s_tok[r];
        const float p = s_p[r];
        float* orow = out + ((size_t)b * T_ + tok) * C_ + n0 + tc;
#pragma unroll
        for (int j = 0; j < 8; j++)
            atomicAdd(orow + j, acc[i][j] * p);
    }
}

// ---------------- zero-init output (poisoned to 0xAA by harness) ----------------
__global__ void zero_kernel(float4* __restrict__ out, int n4) {
    int i = blockIdx.x * blockDim.x + threadIdx.x;
    if (i < n4) out[i] = make_float4(0.f, 0.f, 0.f, 0.f);
}

extern "C" void kernel_launch(void* const* d_in, const int* in_sizes, int n_in,
                              void* d_out, int out_size) {
    const float* x   = (const float*)d_in[0];
    const float* gw  = (const float*)d_in[1];
    const float* w1  = (const float*)d_in[2];
    const float* w2  = (const float*)d_in[3];
    float* out = (float*)d_out;

    const int n4 = (B_ * T_ * C_) / 4;                        // 4,194,304 float4
    zero_kernel<<<(n4 + 255) / 256, 256>>>((float4*)out, n4);

    gate_kernel<<<(B_ * T_) / 8, 256>>>(x, gw);
    topk_kernel<<<B_ * E_, 1024>>>();

    dim3 grid1(H_ / 128, CAP_ / 128, B_ * E_);                // (32, 8, 32)
    gemm1_gelu<<<grid1, 256>>>(x, w1);

    dim3 grid2(C_ / 128, CAP_ / 128, B_ * E_);                // (8, 8, 32)
    gemm2_scatter<<<grid2, 256>>>(w2, out);
}

// round 5
// speedup vs baseline: 1.1598x; 1.1598x over previous
#include <cuda_runtime.h>
#include <cuda_bf16.h>
#include <math.h>
#include <stdint.h>

#define B_   4
#define T_   4096
#define C_   1024
#define H_   4096
#define E_   8
#define CAP_ 1024
#define G_   32
#define BK_  32
#define S_   40            // smem row stride (elements): fragment reads conflict-free

// ======== scratch: EXACTLY round-1's set (proven to load & run) ========
__device__ float g_probs[B_ * E_ * T_];
__device__ float g_topp[G_ * CAP_];
__device__ int   g_topi[G_ * CAP_];
__device__ float g_h[(size_t)G_ * CAP_ * H_];     // 512 MB fp32 hidden acts

// ======== helpers ========
__device__ __forceinline__ void split_bf16(float v, __nv_bfloat16& h, __nv_bfloat16& l) {
    h = __float2bfloat16(v);
    l = __float2bfloat16(v - __bfloat162float(h));
}
__device__ __forceinline__ float gelu_f(float v) {
    return 0.5f * v * (1.0f + erff(v * 0.70710678118654752f));
}
__device__ __forceinline__ uint32_t lds32(const __nv_bfloat16* s, int r, int c) {
    return *(const uint32_t*)(s + r * S_ + c);
}
__device__ __forceinline__ void mma16816(float* d, const uint32_t* a, const uint32_t* b) {
    asm volatile("mma.sync.aligned.m16n8k16.row.col.f32.bf16.bf16.f32 "
        "{%0,%1,%2,%3}, {%4,%5,%6,%7}, {%8,%9}, {%0,%1,%2,%3};"
        : "+f"(d[0]), "+f"(d[1]), "+f"(d[2]), "+f"(d[3])
        : "r"(a[0]), "r"(a[1]), "r"(a[2]), "r"(a[3]), "r"(b[0]), "r"(b[1]));
}

// ======== gate + softmax (identical round 1, proven) ========
__global__ __launch_bounds__(256) void gate_kernel(const float* __restrict__ x,
                                                   const float* __restrict__ gw) {
    __shared__ float sgw[E_][C_];
    for (int i = threadIdx.x; i < C_ * E_; i += 256) {
        int c = i >> 3, e = i & 7;
        sgw[e][c] = gw[i];
    }
    __syncthreads();
    const int warp = threadIdx.x >> 5, lane = threadIdx.x & 31;
    const int token = blockIdx.x * 8 + warp;
    const float* xrow = x + (size_t)token * C_;
    float acc[E_];
#pragma unroll
    for (int e = 0; e < E_; e++) acc[e] = 0.f;
    for (int c = lane; c < C_; c += 32) {
        float xv = xrow[c];
#pragma unroll
        for (int e = 0; e < E_; e++) acc[e] = fmaf(xv, sgw[e][c], acc[e]);
    }
#pragma unroll
    for (int off = 16; off > 0; off >>= 1)
#pragma unroll
        for (int e = 0; e < E_; e++) acc[e] += __shfl_xor_sync(0xffffffffu, acc[e], off);
    if (lane == 0) {
        float mx = acc[0];
#pragma unroll
        for (int e = 1; e < E_; e++) mx = fmaxf(mx, acc[e]);
        float s = 0.f, ex[E_];
#pragma unroll
        for (int e = 0; e < E_; e++) { ex[e] = expf(acc[e] - mx); s += ex[e]; }
        float inv = 1.0f / s;
        const int b = token >> 12, t = token & (T_ - 1);
#pragma unroll
        for (int e = 0; e < E_; e++)
            g_probs[((size_t)(b * E_ + e)) * T_ + t] = ex[e] * inv;
    }
}

// ======== top-k bitonic (identical round 1, proven) ========
__global__ __launch_bounds__(1024) void topk_kernel() {
    __shared__ unsigned long long keys[T_];
    const int g = blockIdx.x;
    const float* p = g_probs + (size_t)g * T_;
    for (int i = threadIdx.x; i < T_; i += 1024) {
        unsigned pb = __float_as_uint(p[i]);
        keys[i] = ((unsigned long long)pb << 32) | (unsigned)(0xFFFFFFFFu - (unsigned)i);
    }
    __syncthreads();
    for (int k = 2; k <= T_; k <<= 1)
        for (int j = k >> 1; j > 0; j >>= 1) {
            for (int i = threadIdx.x; i < T_; i += 1024) {
                int ixj = i ^ j;
                if (ixj > i) {
                    unsigned long long a = keys[i], bb = keys[ixj];
                    bool dsc = ((i & k) == 0);
                    if (dsc ? (a < bb) : (a > bb)) { keys[i] = bb; keys[ixj] = a; }
                }
            }
            __syncthreads();
        }
    for (int i = threadIdx.x; i < CAP_; i += 1024) {
        unsigned long long kv = keys[i];
        g_topp[(size_t)g * CAP_ + i] = __uint_as_float((unsigned)(kv >> 32));
        g_topi[(size_t)g * CAP_ + i] = (int)(0xFFFFFFFFu - (unsigned)kv);
    }
}

// ======== shared MMA tile core ========
// CTA 128x128, BK=32, 256 threads / 8 warps (4m x 2n warp grid, warp tile 32x64).
// fp32 global -> in-register bf16 hi/lo split -> smem; single buffer, reg prefetch.
// A staged [m][k]; B staged transposed [n][k] (global B is [k][n] row-major).
__device__ __forceinline__ void mma_tile(
    const float* __restrict__ aRow,   // this thread's A row ptr (+ half*16 applied)
    const float* __restrict__ bPos,   // this thread's B ptr: Bbase + kr*nstride + ncol
    int nstride, int nkb,
    __nv_bfloat16* sAh, __nv_bfloat16* sAl,
    __nv_bfloat16* sBh, __nv_bfloat16* sBl,
    float acc[2][8][4])
{
    const int tid  = threadIdx.x;
    const int warp = tid >> 5, lane = tid & 31;
    const int gq = lane >> 2, tq = lane & 3;
    const int m_off = (warp >> 1) * 32;
    const int n_off = (warp & 1) * 64;
    const int soA = (tid >> 1) * S_ + (tid & 1) * 16;   // A: row tid>>1, k-half tid&1
    const int kr  = tid >> 3, nc0 = (tid & 7) * 16;     // B: k-row tid>>3, 16 n-cols

    float fa[16], fb[16];
#pragma unroll
    for (int q = 0; q < 4; q++) *(float4*)(fa + 4 * q) = ((const float4*)aRow)[q];
#pragma unroll
    for (int q = 0; q < 4; q++) *(float4*)(fb + 4 * q) = ((const float4*)bPos)[q];

    for (int kb = 0; kb < nkb; kb++) {
        // ---- convert + store A [m][k] ----
        __align__(16) __nv_bfloat16 hb[16], lb[16];
#pragma unroll
        for (int j = 0; j < 16; j++) split_bf16(fa[j], hb[j], lb[j]);
        *(uint4*)(sAh + soA)     = ((uint4*)hb)[0];
        *(uint4*)(sAh + soA + 8) = ((uint4*)hb)[1];
        *(uint4*)(sAl + soA)     = ((uint4*)lb)[0];
        *(uint4*)(sAl + soA + 8) = ((uint4*)lb)[1];
        // ---- convert + store B transposed [n][k] ----
#pragma unroll
        for (int j = 0; j < 16; j++) {
            __nv_bfloat16 h, l;
            split_bf16(fb[j], h, l);
            sBh[(nc0 + j) * S_ + kr] = h;
            sBl[(nc0 + j) * S_ + kr] = l;
        }
        __syncthreads();

        if (kb + 1 < nkb) {
            const float* an = aRow + (size_t)(kb + 1) * BK_;
            const float* bn = bPos + (size_t)(kb + 1) * BK_ * nstride;
#pragma unroll
            for (int q = 0; q < 4; q++) *(float4*)(fa + 4 * q) = ((const float4*)an)[q];
#pragma unroll
            for (int q = 0; q < 4; q++) *(float4*)(fb + 4 * q) = ((const float4*)bn)[q];
        }

#pragma unroll
        for (int ks = 0; ks < BK_; ks += 16) {
            uint32_t ah[2][4], al[2][4];
#pragma unroll
            for (int mt = 0; mt < 2; mt++) {
                const int rb = m_off + mt * 16 + gq;
                const int cb = ks + tq * 2;
                ah[mt][0] = lds32(sAh, rb,     cb);
                ah[mt][1] = lds32(sAh, rb + 8, cb);
                ah[mt][2] = lds32(sAh, rb,     cb + 8);
                ah[mt][3] = lds32(sAh, rb + 8, cb + 8);
                al[mt][0] = lds32(sAl, rb,     cb);
                al[mt][1] = lds32(sAl, rb + 8, cb);
                al[mt][2] = lds32(sAl, rb,     cb + 8);
                al[mt][3] = lds32(sAl, rb + 8, cb + 8);
            }
#pragma unroll
            for (int nt = 0; nt < 8; nt++) {
                const int nb = n_off + nt * 8 + gq;
                const int cb = ks + tq * 2;
                uint32_t bh[2], bl[2];
                bh[0] = lds32(sBh, nb, cb); bh[1] = lds32(sBh, nb, cb + 8);
                bl[0] = lds32(sBl, nb, cb); bl[1] = lds32(sBl, nb, cb + 8);
#pragma unroll
                for (int mt = 0; mt < 2; mt++) {
                    mma16816(acc[mt][nt], ah[mt], bh);
                    mma16816(acc[mt][nt], ah[mt], bl);
                    mma16816(acc[mt][nt], al[mt], bh);
                }
            }
        }
        __syncthreads();
    }
}

// ======== GEMM1: g_h = gelu(gather(x) @ w1[e]), M=1024 N=4096 K=1024 ========
__global__ __launch_bounds__(256) void gemm1_mma(const float* __restrict__ x,
                                                 const float* __restrict__ w1) {
    __shared__ __align__(16) __nv_bfloat16 sAh[128 * S_], sAl[128 * S_];
    __shared__ __align__(16) __nv_bfloat16 sBh[128 * S_], sBl[128 * S_];
    __shared__ int s_row[128];

    const int tid = threadIdx.x;
    const int g = blockIdx.z, b = g >> 3, e = g & 7;
    const int m0 = blockIdx.y << 7, n0 = blockIdx.x << 7;
    if (tid < 128) s_row[tid] = g_topi[(size_t)g * CAP_ + m0 + tid];
    __syncthreads();

    const float* aRow = x + ((size_t)(b * T_ + s_row[tid >> 1])) * C_ + (tid & 1) * 16;
    const float* bPos = w1 + (size_t)e * C_ * H_ + (size_t)(tid >> 3) * H_ + n0 + (tid & 7) * 16;

    float acc[2][8][4];
#pragma unroll
    for (int mt = 0; mt < 2; mt++)
#pragma unroll
        for (int nt = 0; nt < 8; nt++)
#pragma unroll
            for (int i = 0; i < 4; i++) acc[mt][nt][i] = 0.f;

    mma_tile(aRow, bPos, H_, C_ / BK_, sAh, sAl, sBh, sBl, acc);

    const int warp = tid >> 5, lane = tid & 31;
    const int gq = lane >> 2, tq = lane & 3;
    const int m_off = (warp >> 1) * 32, n_off = (warp & 1) * 64;
#pragma unroll
    for (int mt = 0; mt < 2; mt++) {
        const int r0l = m_off + mt * 16 + gq;
#pragma unroll
        for (int nt = 0; nt < 8; nt++) {
            const int col = n0 + n_off + nt * 8 + tq * 2;
#pragma unroll
            for (int hrow = 0; hrow < 2; hrow++) {
                const int rl = r0l + hrow * 8;
                float2 v;
                v.x = gelu_f(acc[mt][nt][2 * hrow + 0]);
                v.y = gelu_f(acc[mt][nt][2 * hrow + 1]);
                *(float2*)(g_h + ((size_t)g * CAP_ + m0 + rl) * H_ + col) = v;
            }
        }
    }
}

// ======== GEMM2: out[b,tok] += p * (g_h @ w2[e]), M=1024 N=1024 K=4096 ========
__global__ __launch_bounds__(256) void gemm2_mma(const float* __restrict__ w2,
                                                 float* __restrict__ out) {
    __shared__ __align__(16) __nv_bfloat16 sAh[128 * S_], sAl[128 * S_];
    __shared__ __align__(16) __nv_bfloat16 sBh[128 * S_], sBl[128 * S_];
    __shared__ int   s_tok[128];
    __shared__ float s_p[128];

    const int tid = threadIdx.x;
    const int g = blockIdx.z, b = g >> 3, e = g & 7;
    const int m0 = blockIdx.y << 7, n0 = blockIdx.x << 7;
    if (tid < 128) {
        s_tok[tid] = g_topi[(size_t)g * CAP_ + m0 + tid];
        s_p[tid]   = g_topp[(size_t)g * CAP_ + m0 + tid];
    }
    __syncthreads();

    const float* aRow = g_h + ((size_t)g * CAP_ + m0 + (tid >> 1)) * H_ + (tid & 1) * 16;
    const float* bPos = w2 + (size_t)e * H_ * C_ + (size_t)(tid >> 3) * C_ + n0 + (tid & 7) * 16;

    float acc[2][8][4];
#pragma unroll
    for (int mt = 0; mt < 2; mt++)
#pragma unroll
        for (int nt = 0; nt < 8; nt++)
#pragma unroll
            for (int i = 0; i < 4; i++) acc[mt][nt][i] = 0.f;

    mma_tile(aRow, bPos, C_, H_ / BK_, sAh, sAl, sBh, sBl, acc);

    const int warp = tid >> 5, lane = tid & 31;
    const int gq = lane >> 2, tq = lane & 3;
    const int m_off = (warp >> 1) * 32, n_off = (warp & 1) * 64;
#pragma unroll
    for (int mt = 0; mt < 2; mt++) {
        const int r0l = m_off + mt * 16 + gq;
#pragma unroll
        for (int nt = 0; nt < 8; nt++) {
            const int col = n0 + n_off + nt * 8 + tq * 2;
#pragma unroll
            for (int hrow = 0; hrow < 2; hrow++) {
                const int rl = r0l + hrow * 8;
                const int tok = s_tok[rl];
                const float p = s_p[rl];
                float* orow = out + ((size_t)b * T_ + tok) * C_ + col;
                atomicAdd(orow,     acc[mt][nt][2 * hrow + 0] * p);
                atomicAdd(orow + 1, acc[mt][nt][2 * hrow + 1] * p);
            }
        }
    }
}

// ======== zero-init output ========
__global__ void zero_kernel(float4* __restrict__ out, int n4) {
    int i = blockIdx.x * blockDim.x + threadIdx.x;
    if (i < n4) out[i] = make_float4(0.f, 0.f, 0.f, 0.f);
}

// ======== launch ========
extern "C" void kernel_launch(void* const* d_in, const int* in_sizes, int n_in,
                              void* d_out, int out_size) {
    const float* x  = (const float*)d_in[0];
    const float* gw = (const float*)d_in[1];
    const float* w1 = (const float*)d_in[2];
    const float* w2 = (const float*)d_in[3];
    float* out = (float*)d_out;

    const int n4 = (B_ * T_ * C_) / 4;
    zero_kernel<<<(n4 + 255) / 256, 256>>>((float4*)out, n4);

    gate_kernel<<<(B_ * T_) / 8, 256>>>(x, gw);
    topk_kernel<<<G_, 1024>>>();

    gemm1_mma<<<dim3(H_ / 128, CAP_ / 128, G_), 256>>>(x, w1);
    gemm2_mma<<<dim3(C_ / 128, CAP_ / 128, G_), 256>>>(w2, out);
}

// round 6
// speedup vs baseline: 2.0113x; 1.7342x over previous
#include <cuda_runtime.h>
#include <cuda_bf16.h>
#include <math.h>
#include <stdint.h>

#define B_   4
#define T_   4096
#define C_   1024
#define H_   4096
#define E_   8
#define CAP_ 1024
#define G_   32
#define BK_  32
#define S_   40            // A smem row stride (elements), conflict-free for LDSM
#define SB_  136           // B smem row stride (elements), conflict-free for LDSM.trans

// ======== scratch: EXACTLY round-1/5's set (proven to load & run) ========
__device__ float g_probs[B_ * E_ * T_];
__device__ float g_topp[G_ * CAP_];
__device__ int   g_topi[G_ * CAP_];
__device__ float g_h[(size_t)G_ * CAP_ * H_];     // 512 MB fp32 hidden acts

// ======== helpers ========
__device__ __forceinline__ uint32_t smem_u32(const void* p) {
    uint32_t a;
    asm("{ .reg .u64 t; cvta.to.shared.u64 t, %1; cvt.u32.u64 %0, t; }" : "=r"(a) : "l"(p));
    return a;
}
__device__ __forceinline__ void split_bf16(float v, __nv_bfloat16& h, __nv_bfloat16& l) {
    h = __float2bfloat16(v);
    l = __float2bfloat16(v - __bfloat162float(h));
}
__device__ __forceinline__ float gelu_f(float v) {
    return 0.5f * v * (1.0f + erff(v * 0.70710678118654752f));
}
__device__ __forceinline__ void mma16816(float* d, const uint32_t* a, const uint32_t* b) {
    asm volatile("mma.sync.aligned.m16n8k16.row.col.f32.bf16.bf16.f32 "
        "{%0,%1,%2,%3}, {%4,%5,%6,%7}, {%8,%9}, {%0,%1,%2,%3};"
        : "+f"(d[0]), "+f"(d[1]), "+f"(d[2]), "+f"(d[3])
        : "r"(a[0]), "r"(a[1]), "r"(a[2]), "r"(a[3]), "r"(b[0]), "r"(b[1]));
}
#define LDSM_X4(r, addr) \
    asm volatile("ldmatrix.sync.aligned.m8n8.x4.shared.b16 {%0,%1,%2,%3}, [%4];" \
        : "=r"((r)[0]), "=r"((r)[1]), "=r"((r)[2]), "=r"((r)[3]) : "r"(addr))
#define LDSM_X4_T(r, addr) \
    asm volatile("ldmatrix.sync.aligned.m8n8.x4.trans.shared.b16 {%0,%1,%2,%3}, [%4];" \
        : "=r"((r)[0]), "=r"((r)[1]), "=r"((r)[2]), "=r"((r)[3]) : "r"(addr))

// ======== gate + softmax (identical, proven) ========
__global__ __launch_bounds__(256) void gate_kernel(const float* __restrict__ x,
                                                   const float* __restrict__ gw) {
    __shared__ float sgw[E_][C_];
    for (int i = threadIdx.x; i < C_ * E_; i += 256) {
        int c = i >> 3, e = i & 7;
        sgw[e][c] = gw[i];
    }
    __syncthreads();
    const int warp = threadIdx.x >> 5, lane = threadIdx.x & 31;
    const int token = blockIdx.x * 8 + warp;
    const float* xrow = x + (size_t)token * C_;
    float acc[E_];
#pragma unroll
    for (int e = 0; e < E_; e++) acc[e] = 0.f;
    for (int c = lane; c < C_; c += 32) {
        float xv = xrow[c];
#pragma unroll
        for (int e = 0; e < E_; e++) acc[e] = fmaf(xv, sgw[e][c], acc[e]);
    }
#pragma unroll
    for (int off = 16; off > 0; off >>= 1)
#pragma unroll
        for (int e = 0; e < E_; e++) acc[e] += __shfl_xor_sync(0xffffffffu, acc[e], off);
    if (lane == 0) {
        float mx = acc[0];
#pragma unroll
        for (int e = 1; e < E_; e++) mx = fmaxf(mx, acc[e]);
        float s = 0.f, ex[E_];
#pragma unroll
        for (int e = 0; e < E_; e++) { ex[e] = expf(acc[e] - mx); s += ex[e]; }
        float inv = 1.0f / s;
        const int b = token >> 12, t = token & (T_ - 1);
#pragma unroll
        for (int e = 0; e < E_; e++)
            g_probs[((size_t)(b * E_ + e)) * T_ + t] = ex[e] * inv;
    }
}

// ======== top-k bitonic (identical, proven) ========
__global__ __launch_bounds__(1024) void topk_kernel() {
    __shared__ unsigned long long keys[T_];
    const int g = blockIdx.x;
    const float* p = g_probs + (size_t)g * T_;
    for (int i = threadIdx.x; i < T_; i += 1024) {
        unsigned pb = __float_as_uint(p[i]);
        keys[i] = ((unsigned long long)pb << 32) | (unsigned)(0xFFFFFFFFu - (unsigned)i);
    }
    __syncthreads();
    for (int k = 2; k <= T_; k <<= 1)
        for (int j = k >> 1; j > 0; j >>= 1) {
            for (int i = threadIdx.x; i < T_; i += 1024) {
                int ixj = i ^ j;
                if (ixj > i) {
                    unsigned long long a = keys[i], bb = keys[ixj];
                    bool dsc = ((i & k) == 0);
                    if (dsc ? (a < bb) : (a > bb)) { keys[i] = bb; keys[ixj] = a; }
                }
            }
            __syncthreads();
        }
    for (int i = threadIdx.x; i < CAP_; i += 1024) {
        unsigned long long kv = keys[i];
        g_topp[(size_t)g * CAP_ + i] = __uint_as_float((unsigned)(kv >> 32));
        g_topi[(size_t)g * CAP_ + i] = (int)(0xFFFFFFFFu - (unsigned)kv);
    }
}

// ======== MMA tile core (new: vectorized B staging [k][n] + LDSM fragments) ========
// CTA 128x128, BK=32, 256 threads / 8 warps (4m x 2n, warp tile 32x64).
// A staged [m][S_]; B staged [k][SB_] untransposed; ldmatrix(.trans) fragment loads.
__device__ __forceinline__ void mma_tile(
    const float* __restrict__ aRow,   // A row ptr for this thread (+half*16 applied)
    const float* __restrict__ bPos,   // B ptr: base + (tid>>3)*nstride + ncol
    int nstride, int nkb,
    __nv_bfloat16* sAh, __nv_bfloat16* sAl,
    __nv_bfloat16* sBh, __nv_bfloat16* sBl,
    float acc[2][8][4])
{
    const int tid  = threadIdx.x;
    const int warp = tid >> 5, lane = tid & 31;
    const int m_off = (warp >> 1) * 32;
    const int n_off = (warp & 1) * 64;
    const int soA = (tid >> 1) * S_ + (tid & 1) * 16;   // A store: row tid>>1, k-half tid&1
    const int soB = (tid >> 3) * SB_ + (tid & 7) * 16;  // B store: k-row tid>>3, 16 n

    // ldmatrix per-lane address offsets (bytes)
    const uint32_t bAh = smem_u32(sAh), bAl = smem_u32(sAl);
    const uint32_t bBh = smem_u32(sBh), bBl = smem_u32(sBl);
    const uint32_t aoff = (uint32_t)(((m_off + (lane & 15)) * S_ + ((lane & 16) ? 8 : 0)) * 2);
    const uint32_t boff = (uint32_t)(((lane & 15) * SB_ + n_off + ((lane & 16) ? 8 : 0)) * 2);

    float fa[16], fb[16];
#pragma unroll
    for (int q = 0; q < 4; q++) *(float4*)(fa + 4 * q) = ((const float4*)aRow)[q];
#pragma unroll
    for (int q = 0; q < 4; q++) *(float4*)(fb + 4 * q) = ((const float4*)bPos)[q];

    for (int kb = 0; kb < nkb; kb++) {
        // ---- convert + store A [m][k], B [k][n] (both vectorized, conflict-free) ----
        __align__(16) __nv_bfloat16 ha[16], la[16];
#pragma unroll
        for (int j = 0; j < 16; j++) split_bf16(fa[j], ha[j], la[j]);
        *(uint4*)(sAh + soA)     = ((uint4*)ha)[0];
        *(uint4*)(sAh + soA + 8) = ((uint4*)ha)[1];
        *(uint4*)(sAl + soA)     = ((uint4*)la)[0];
        *(uint4*)(sAl + soA + 8) = ((uint4*)la)[1];
#pragma unroll
        for (int j = 0; j < 16; j++) split_bf16(fb[j], ha[j], la[j]);
        *(uint4*)(sBh + soB)     = ((uint4*)ha)[0];
        *(uint4*)(sBh + soB + 8) = ((uint4*)ha)[1];
        *(uint4*)(sBl + soB)     = ((uint4*)la)[0];
        *(uint4*)(sBl + soB + 8) = ((uint4*)la)[1];
        __syncthreads();

        if (kb + 1 < nkb) {
            const float* an = aRow + (size_t)(kb + 1) * BK_;
            const float* bn = bPos + (size_t)(kb + 1) * BK_ * nstride;
#pragma unroll
            for (int q = 0; q < 4; q++) *(float4*)(fa + 4 * q) = ((const float4*)an)[q];
#pragma unroll
            for (int q = 0; q < 4; q++) *(float4*)(fb + 4 * q) = ((const float4*)bn)[q];
        }

#pragma unroll
        for (int ks = 0; ks < BK_; ks += 16) {
            uint32_t ah[2][4], al[2][4];
#pragma unroll
            for (int mt = 0; mt < 2; mt++) {
                const uint32_t aadd = aoff + (uint32_t)((mt * 16 * S_ + ks) * 2);
                LDSM_X4(ah[mt], bAh + aadd);
                LDSM_X4(al[mt], bAl + aadd);
            }
#pragma unroll
            for (int pair = 0; pair < 4; pair++) {
                uint32_t bh[4], bl[4];
                const uint32_t badd = boff + (uint32_t)((ks * SB_ + pair * 16) * 2);
                LDSM_X4_T(bh, bBh + badd);
                LDSM_X4_T(bl, bBl + badd);
#pragma unroll
                for (int sub = 0; sub < 2; sub++) {
                    const int nt = pair * 2 + sub;
#pragma unroll
                    for (int mt = 0; mt < 2; mt++) {
                        mma16816(acc[mt][nt], ah[mt], bh + 2 * sub);
                        mma16816(acc[mt][nt], ah[mt], bl + 2 * sub);
                        mma16816(acc[mt][nt], al[mt], bh + 2 * sub);
                    }
                }
            }
        }
        __syncthreads();
    }
}

// ======== GEMM1: g_h = gelu(gather(x) @ w1[e]), M=1024 N=4096 K=1024 ========
__global__ __launch_bounds__(256) void gemm1_mma(const float* __restrict__ x,
                                                 const float* __restrict__ w1) {
    __shared__ __align__(16) __nv_bfloat16 sAh[128 * S_], sAl[128 * S_];
    __shared__ __align__(16) __nv_bfloat16 sBh[BK_ * SB_], sBl[BK_ * SB_];
    __shared__ int s_row[128];

    const int tid = threadIdx.x;
    const int g = blockIdx.z, b = g >> 3, e = g & 7;
    const int m0 = blockIdx.y << 7, n0 = blockIdx.x << 7;
    if (tid < 128) s_row[tid] = g_topi[(size_t)g * CAP_ + m0 + tid];
    __syncthreads();

    const float* aRow = x + ((size_t)(b * T_ + s_row[tid >> 1])) * C_ + (tid & 1) * 16;
    const float* bPos = w1 + (size_t)e * C_ * H_ + (size_t)(tid >> 3) * H_ + n0 + (tid & 7) * 16;

    float acc[2][8][4];
#pragma unroll
    for (int mt = 0; mt < 2; mt++)
#pragma unroll
        for (int nt = 0; nt < 8; nt++)
#pragma unroll
            for (int i = 0; i < 4; i++) acc[mt][nt][i] = 0.f;

    mma_tile(aRow, bPos, H_, C_ / BK_, sAh, sAl, sBh, sBl, acc);

    const int warp = tid >> 5, lane = tid & 31;
    const int gq = lane >> 2, tq = lane & 3;
    const int m_off = (warp >> 1) * 32, n_off = (warp & 1) * 64;
#pragma unroll
    for (int mt = 0; mt < 2; mt++) {
        const int r0l = m_off + mt * 16 + gq;
#pragma unroll
        for (int nt = 0; nt < 8; nt++) {
            const int col = n0 + n_off + nt * 8 + tq * 2;
#pragma unroll
            for (int hrow = 0; hrow < 2; hrow++) {
                const int rl = r0l + hrow * 8;
                float2 v;
                v.x = gelu_f(acc[mt][nt][2 * hrow + 0]);
                v.y = gelu_f(acc[mt][nt][2 * hrow + 1]);
                *(float2*)(g_h + ((size_t)g * CAP_ + m0 + rl) * H_ + col) = v;
            }
        }
    }
}

// ======== GEMM2: out[b,tok] += p * (g_h @ w2[e]), M=1024 N=1024 K=4096 ========
__global__ __launch_bounds__(256) void gemm2_mma(const float* __restrict__ w2,
                                                 float* __restrict__ out) {
    __shared__ __align__(16) __nv_bfloat16 sAh[128 * S_], sAl[128 * S_];
    __shared__ __align__(16) __nv_bfloat16 sBh[BK_ * SB_], sBl[BK_ * SB_];
    __shared__ int   s_tok[128];
    __shared__ float s_p[128];

    const int tid = threadIdx.x;
    const int g = blockIdx.z, b = g >> 3, e = g & 7;
    const int m0 = blockIdx.y << 7, n0 = blockIdx.x << 7;
    if (tid < 128) {
        s_tok[tid] = g_topi[(size_t)g * CAP_ + m0 + tid];
        s_p[tid]   = g_topp[(size_t)g * CAP_ + m0 + tid];
    }
    __syncthreads();

    const float* aRow = g_h + ((size_t)g * CAP_ + m0 + (tid >> 1)) * H_ + (tid & 1) * 16;
    const float* bPos = w2 + (size_t)e * H_ * C_ + (size_t)(tid >> 3) * C_ + n0 + (tid & 7) * 16;

    float acc[2][8][4];
#pragma unroll
    for (int mt = 0; mt < 2; mt++)
#pragma unroll
        for (int nt = 0; nt < 8; nt++)
#pragma unroll
            for (int i = 0; i < 4; i++) acc[mt][nt][i] = 0.f;

    mma_tile(aRow, bPos, C_, H_ / BK_, sAh, sAl, sBh, sBl, acc);

    const int warp = tid >> 5, lane = tid & 31;
    const int gq = lane >> 2, tq = lane & 3;
    const int m_off = (warp >> 1) * 32, n_off = (warp & 1) * 64;
#pragma unroll
    for (int mt = 0; mt < 2; mt++) {
        const int r0l = m_off + mt * 16 + gq;
#pragma unroll
        for (int nt = 0; nt < 8; nt++) {
            const int col = n0 + n_off + nt * 8 + tq * 2;
#pragma unroll
            for (int hrow = 0; hrow < 2; hrow++) {
                const int rl = r0l + hrow * 8;
                const int tok = s_tok[rl];
                const float p = s_p[rl];
                float* orow = out + ((size_t)b * T_ + tok) * C_ + col;
                atomicAdd(orow,     acc[mt][nt][2 * hrow + 0] * p);
                atomicAdd(orow + 1, acc[mt][nt][2 * hrow + 1] * p);
            }
        }
    }
}

// ======== zero-init output ========
__global__ void zero_kernel(float4* __restrict__ out, int n4) {
    int i = blockIdx.x * blockDim.x + threadIdx.x;
    if (i < n4) out[i] = make_float4(0.f, 0.f, 0.f, 0.f);
}

// ======== launch ========
extern "C" void kernel_launch(void* const* d_in, const int* in_sizes, int n_in,
                              void* d_out, int out_size) {
    const float* x  = (const float*)d_in[0];
    const float* gw = (const float*)d_in[1];
    const float* w1 = (const float*)d_in[2];
    const float* w2 = (const float*)d_in[3];
    float* out = (float*)d_out;

    const int n4 = (B_ * T_ * C_) / 4;
    zero_kernel<<<(n4 + 255) / 256, 256>>>((float4*)out, n4);

    gate_kernel<<<(B_ * T_) / 8, 256>>>(x, gw);
    topk_kernel<<<G_, 1024>>>();

    gemm1_mma<<<dim3(H_ / 128, CAP_ / 128, G_), 256>>>(x, w1);
    gemm2_mma<<<dim3(C_ / 128, CAP_ / 128, G_), 256>>>(w2, out);
}